// round 11
// baseline (speedup 1.0000x reference)
#include <cuda_runtime.h>
#include <math.h>
#include <stdint.h>

// ---------------- dimensions ----------------
#define NB   32
#define C0   2
#define H0   400
#define W0   600
#define KH1  10
#define KW1  11
#define H1   50
#define W1   66
#define OC1  64
#define POS1 (NB*H1*W1)          // 105600
#define K1   (KH1*KW1*C0)        // 220
#define H2   5
#define W2   6
#define POS2 (NB*H2*W2)          // 960
#define K2   (12*12*64)          // 9216
#define KE   512
#define TH   50
#define TW   60
#define POSD (NB*TH*TW)          // 96000
#define NT1  (12*12*64)          // 9216
#define NT2  (10*11*2)           // 220
#define OHH  400
#define OWW  540
#define RECON_N (NB*2*OHH*OWW)   // 13824000

// ---------------- scratch ----------------
__device__ float g_h1  [(size_t)POS1*OC1];
__device__ float g_col [(size_t)POS2*K2];
__device__ float g_hA  [POS2*128];
__device__ float g_hB  [POS2*128];
__device__ float g_t64 [POS2*64];
__device__ float g_z   [POS2*64];
__device__ float g_q   [POS2*64];
__device__ float g_part[8*POS2*128];
__device__ float g_Y1  [(size_t)POS2*NT1];
__device__ float g_t1  [(size_t)POSD*64];
__device__ float g_Y2  [(size_t)POSD*NT2];
__device__ float g_w1t [K1*OC1];
__device__ float g_w2t [K2*128];
__device__ float g_w3t [9*128*128];
__device__ float g_er1t[2*9*128*64];
__device__ float g_er2t[2*64*128];
__device__ float g_pret[128*64];
__device__ float g_d1t [9*64*128];
__device__ float g_dr1t[2*9*128*64];
__device__ float g_dr2t[2*64*128];
__device__ float g_tw1t[128*NT1];
__device__ float g_tw2t[64*NT2];
__device__ float g_esq [KE];
__device__ int   g_counts[KE];
__device__ float g_sqacc[1];
__device__ int   g_idx [POS2];

// ---------------- merged weight transpose ----------------
#define NJOBS 15
struct TJobs {
    const float* src[NJOBS];
    float*       dst[NJOBS];
    int cout[NJOBS], cin[NJOBS], kh[NJOBS], kw[NJOBS], isT[NJOBS];
    long off[NJOBS+1];
};

__global__ void wtrans_all_kernel(TJobs J) {
    long t = (long)blockIdx.x * blockDim.x + threadIdx.x;
    if (t >= J.off[NJOBS]) return;
    int j = 0;
#pragma unroll
    for (int i = 0; i < NJOBS-1; i++) j += (t >= J.off[i+1]) ? 1 : 0;
    long u = t - J.off[j];
    int Cout = J.cout[j], Cin = J.cin[j], KH = J.kh[j], KW = J.kw[j];
    int oc = (int)(u % Cout); long r = u / Cout;
    if (!J.isT[j]) {
        int ic = (int)(r % Cin);
        int kk = (int)(r / Cin);
        int khh = kk / KW, kww = kk % KW;
        J.dst[j][u] = J.src[j][((oc*Cin + ic)*KH + khh)*KW + kww];
    } else {
        int khw = KH*KW;
        int kk = (int)(r % khw);
        int ic = (int)(r / khw);
        J.dst[j][u] = J.src[j][(ic*Cout + oc)*khw + kk];
    }
}

// ---------------- implicit conv1: fp32 gemm128 with fused im2col A-loader ----------------
// C[pos][oc] = relu( sum_k A(pos,k) * w1t[k][oc] + b[oc] ), A(pos,k) generated from x.
// k = (kh*11+kw)*2 + ic. N=64 (single tile in x-dim).
__global__ __launch_bounds__(128)
void conv1_kernel(const float* __restrict__ x, const float* __restrict__ B,
                  float* __restrict__ C, const float* __restrict__ bias)
{
    __shared__ float As[128][17];
    __shared__ float Bs[16][64];
    const int M = POS1, N = OC1, K = K1;
    int m0 = blockIdx.y * 128;
    int tid = threadIdx.x;
    int tym = tid >> 3;
    int txn = tid & 7;
    float acc[8][8];
#pragma unroll
    for (int i = 0; i < 8; i++)
#pragma unroll
        for (int j = 0; j < 8; j++) acc[i][j] = 0.f;

    for (int k0 = 0; k0 < K; k0 += 16) {
        // A tile 128x16 generated from x
#pragma unroll
        for (int r = 0; r < 16; r++) {
            int t = tid + r*128;
            int m = t >> 4, k = t & 15;
            int gm = m0 + m, gk = k0 + k;
            float v = 0.f;
            if (gm < M && gk < K) {
                int ow = gm % W1;
                int r2 = gm / W1;
                int oh = r2 % H1;
                int b  = r2 / H1;
                int ic  = gk & 1;
                int khw = gk >> 1;
                int kw = khw % 11;
                int kh = khw / 11;
                int ih = oh*8 - 1 + kh;
                int iw = ow*9 - 1 + kw;
                if (ih >= 0 && ih < H0 && iw >= 0 && iw < W0)
                    v = x[(((long)(b*2 + ic))*H0 + ih)*W0 + iw];
            }
            As[m][k] = v;
        }
        // B tile 16x64
        {
            int n = tid & 63;
            int kb = tid >> 6;
#pragma unroll
            for (int r = 0; r < 8; r++) {
                int k = kb + r*2;
                int gk = k0 + k;
                Bs[k][n] = (gk < K) ? B[(size_t)gk*N + n] : 0.f;
            }
        }
        __syncthreads();
#pragma unroll
        for (int kk = 0; kk < 16; kk++) {
            float a[8], b[8];
#pragma unroll
            for (int i = 0; i < 8; i++) a[i] = As[tym*8 + i][kk];
            float4 b0 = *(const float4*)&Bs[kk][txn*8];
            float4 b1 = *(const float4*)&Bs[kk][txn*8 + 4];
            b[0]=b0.x; b[1]=b0.y; b[2]=b0.z; b[3]=b0.w;
            b[4]=b1.x; b[5]=b1.y; b[6]=b1.z; b[7]=b1.w;
#pragma unroll
            for (int i = 0; i < 8; i++)
#pragma unroll
                for (int j = 0; j < 8; j++)
                    acc[i][j] = fmaf(a[i], b[j], acc[i][j]);
        }
        __syncthreads();
    }
#pragma unroll
    for (int i = 0; i < 8; i++) {
        int gm = m0 + tym*8 + i;
        if (gm >= M) continue;
#pragma unroll
        for (int j = 0; j < 8; j++) {
            int gn = txn*8 + j;
            float v = acc[i][j] + bias[gn];
            C[(size_t)gm*N + gn] = fmaxf(v, 0.f);
        }
    }
}

// ---------------- templated NHWC im2col, 4 channels per thread ----------------
template<int H,int W,int C,int KH,int KW,int SH,int SW,int OH,int OW,int RELU>
__global__ void im2col4_kernel(const float* __restrict__ in, float* __restrict__ out, int total4) {
    int t = blockIdx.x * blockDim.x + threadIdx.x;
    if (t >= total4) return;
    constexpr int KC4 = KH*KW*(C/4);
    int k4  = t % KC4;
    int pos = t / KC4;
    int ic = (k4 % (C/4)) * 4;
    int r  = k4 / (C/4);
    int kw = r % KW;
    int kh = r / KW;
    int ow = pos % OW;
    int r2 = pos / OW;
    int oh = r2 % OH;
    int b  = r2 / OH;
    int ih = oh*SH - 1 + kh;
    int iw = ow*SW - 1 + kw;
    float4 v = make_float4(0.f, 0.f, 0.f, 0.f);
    if (ih >= 0 && ih < H && iw >= 0 && iw < W) {
        v = *(const float4*)(in + (((long)(b*H + ih))*W + iw)*C + ic);
        if (RELU) {
            v.x = fmaxf(v.x, 0.f); v.y = fmaxf(v.y, 0.f);
            v.z = fmaxf(v.z, 0.f); v.w = fmaxf(v.w, 0.f);
        }
    }
    *(float4*)(out + (size_t)t*4) = v;
}

// ---------------- tf32 helpers ----------------
__device__ __forceinline__ uint32_t f2tf32(float x) {
    uint32_t r;
    asm("cvt.rna.tf32.f32 %0, %1;" : "=r"(r) : "f"(x));
    return r;
}
__device__ __forceinline__ void split3(float v, uint32_t& hi, uint32_t& lo) {
    hi = f2tf32(v);
    lo = f2tf32(v - __uint_as_float(hi));
}
#define MMA_TF32(acc, a0,a1,a2,a3, b0,b1) \
    asm volatile( \
        "mma.sync.aligned.m16n8k8.row.col.f32.tf32.tf32.f32 " \
        "{%0,%1,%2,%3}, {%4,%5,%6,%7}, {%8,%9}, {%0,%1,%2,%3};" \
        : "+f"((acc)[0]), "+f"((acc)[1]), "+f"((acc)[2]), "+f"((acc)[3]) \
        : "r"(a0), "r"(a1), "r"(a2), "r"(a3), "r"(b0), "r"(b1))

// ---------------- 3xTF32 GEMM (fp32-accurate, tensor cores) ----------------
__global__ __launch_bounds__(256)
void gemm3x_kernel(const float* __restrict__ A, const float* __restrict__ B,
                   float* __restrict__ C, int M, int N, int K, int Kc,
                   const float* __restrict__ bias, int reluOut, int reluA)
{
    __shared__ float As[128][17];
    __shared__ float Bs[16][72];
    int m0 = blockIdx.y * 128;
    int n0 = blockIdx.x * 64;
    int s  = blockIdx.z;
    int kbeg = s * Kc;
    int kend = kbeg + Kc; if (kend > K) kend = K;
    int tid = threadIdx.x;
    int warp = tid >> 5, lane = tid & 31;
    int wm = warp >> 1, wn = warp & 1;
    int g = lane >> 2, tg = lane & 3;

    float acc[2][4][4];
#pragma unroll
    for (int mi = 0; mi < 2; mi++)
#pragma unroll
        for (int ni = 0; ni < 4; ni++)
#pragma unroll
            for (int c = 0; c < 4; c++) acc[mi][ni][c] = 0.f;

    for (int k0 = kbeg; k0 < kend; k0 += 16) {
#pragma unroll
        for (int r = 0; r < 8; r++) {
            int t = tid + r*256;
            int m = t >> 4, k = t & 15;
            int gm = m0 + m, gk = k0 + k;
            float v = (gm < M && gk < kend) ? A[(size_t)gm*K + gk] : 0.f;
            if (reluA) v = fmaxf(v, 0.f);
            As[m][k] = v;
        }
#pragma unroll
        for (int r = 0; r < 4; r++) {
            int t = tid + r*256;
            int k = t >> 6, n = t & 63;
            int gk = k0 + k, gn = n0 + n;
            Bs[k][n] = (gk < kend && gn < N) ? B[(size_t)gk*N + gn] : 0.f;
        }
        __syncthreads();
#pragma unroll
        for (int kk = 0; kk < 16; kk += 8) {
            uint32_t ah[2][4], al[2][4], bh[4][2], bl[4][2];
#pragma unroll
            for (int mi = 0; mi < 2; mi++) {
                int mrow = wm*32 + mi*16;
                split3(As[mrow + g    ][kk + tg    ], ah[mi][0], al[mi][0]);
                split3(As[mrow + g + 8][kk + tg    ], ah[mi][1], al[mi][1]);
                split3(As[mrow + g    ][kk + tg + 4], ah[mi][2], al[mi][2]);
                split3(As[mrow + g + 8][kk + tg + 4], ah[mi][3], al[mi][3]);
            }
#pragma unroll
            for (int ni = 0; ni < 4; ni++) {
                int ncol = wn*32 + ni*8 + g;
                split3(Bs[kk + tg    ][ncol], bh[ni][0], bl[ni][0]);
                split3(Bs[kk + tg + 4][ncol], bh[ni][1], bl[ni][1]);
            }
#pragma unroll
            for (int mi = 0; mi < 2; mi++)
#pragma unroll
                for (int ni = 0; ni < 4; ni++) {
                    MMA_TF32(acc[mi][ni], ah[mi][0],ah[mi][1],ah[mi][2],ah[mi][3], bl[ni][0],bl[ni][1]);
                    MMA_TF32(acc[mi][ni], al[mi][0],al[mi][1],al[mi][2],al[mi][3], bh[ni][0],bh[ni][1]);
                    MMA_TF32(acc[mi][ni], ah[mi][0],ah[mi][1],ah[mi][2],ah[mi][3], bh[ni][0],bh[ni][1]);
                }
        }
        __syncthreads();
    }
    int splitk = (gridDim.z > 1);
    float* Cs = splitk ? (C + (size_t)s*M*N) : C;
#pragma unroll
    for (int mi = 0; mi < 2; mi++) {
#pragma unroll
        for (int ni = 0; ni < 4; ni++) {
            int gmA = m0 + wm*32 + mi*16 + g;
            int gmB = gmA + 8;
            int gn0 = n0 + wn*32 + ni*8 + 2*tg;
            float v0 = acc[mi][ni][0], v1 = acc[mi][ni][1];
            float v2 = acc[mi][ni][2], v3 = acc[mi][ni][3];
            if (!splitk) {
                if (bias) {
                    float b0 = (gn0 < N) ? bias[gn0] : 0.f;
                    float b1 = (gn0+1 < N) ? bias[gn0+1] : 0.f;
                    v0 += b0; v1 += b1; v2 += b0; v3 += b1;
                }
                if (reluOut) {
                    v0 = fmaxf(v0, 0.f); v1 = fmaxf(v1, 0.f);
                    v2 = fmaxf(v2, 0.f); v3 = fmaxf(v3, 0.f);
                }
            }
            if (gmA < M) {
                if (gn0     < N) Cs[(size_t)gmA*N + gn0    ] = v0;
                if (gn0 + 1 < N) Cs[(size_t)gmA*N + gn0 + 1] = v1;
            }
            if (gmB < M) {
                if (gn0     < N) Cs[(size_t)gmB*N + gn0    ] = v2;
                if (gn0 + 1 < N) Cs[(size_t)gmB*N + gn0 + 1] = v3;
            }
        }
    }
}

// ---------------- plain tf32 GEMM (decoder only) ----------------
__global__ __launch_bounds__(256)
void gemm_tf32_kernel(const float* __restrict__ A, const float* __restrict__ B,
                      float* __restrict__ C, int M, int N, int K, int reluA)
{
    __shared__ uint32_t As[128][17];
    __shared__ uint32_t Bs[16][72];
    int m0 = blockIdx.y * 128;
    int n0 = blockIdx.x * 64;
    int tid = threadIdx.x;
    int warp = tid >> 5, lane = tid & 31;
    int wm = warp >> 1, wn = warp & 1;
    int groupID = lane >> 2, tig = lane & 3;

    float acc[2][4][4];
#pragma unroll
    for (int mi = 0; mi < 2; mi++)
#pragma unroll
        for (int ni = 0; ni < 4; ni++)
#pragma unroll
            for (int c = 0; c < 4; c++) acc[mi][ni][c] = 0.f;

    for (int k0 = 0; k0 < K; k0 += 16) {
#pragma unroll
        for (int r = 0; r < 8; r++) {
            int t = tid + r*256;
            int m = t >> 4, k = t & 15;
            int gm = m0 + m, gk = k0 + k;
            float v = (gm < M && gk < K) ? A[(size_t)gm*K + gk] : 0.f;
            if (reluA) v = fmaxf(v, 0.f);
            As[m][k] = f2tf32(v);
        }
#pragma unroll
        for (int r = 0; r < 4; r++) {
            int t = tid + r*256;
            int k = t >> 6, n = t & 63;
            int gk = k0 + k, gn = n0 + n;
            float v = (gk < K && gn < N) ? B[(size_t)gk*N + gn] : 0.f;
            Bs[k][n] = f2tf32(v);
        }
        __syncthreads();
#pragma unroll
        for (int kk = 0; kk < 16; kk += 8) {
            uint32_t a[2][4], b[4][2];
#pragma unroll
            for (int mi = 0; mi < 2; mi++) {
                int mrow = wm*32 + mi*16;
                a[mi][0] = As[mrow + groupID    ][kk + tig    ];
                a[mi][1] = As[mrow + groupID + 8][kk + tig    ];
                a[mi][2] = As[mrow + groupID    ][kk + tig + 4];
                a[mi][3] = As[mrow + groupID + 8][kk + tig + 4];
            }
#pragma unroll
            for (int ni = 0; ni < 4; ni++) {
                int ncol = wn*32 + ni*8 + groupID;
                b[ni][0] = Bs[kk + tig    ][ncol];
                b[ni][1] = Bs[kk + tig + 4][ncol];
            }
#pragma unroll
            for (int mi = 0; mi < 2; mi++)
#pragma unroll
                for (int ni = 0; ni < 4; ni++)
                    MMA_TF32(acc[mi][ni], a[mi][0],a[mi][1],a[mi][2],a[mi][3], b[ni][0],b[ni][1]);
        }
        __syncthreads();
    }
#pragma unroll
    for (int mi = 0; mi < 2; mi++) {
#pragma unroll
        for (int ni = 0; ni < 4; ni++) {
            int gmA = m0 + wm*32 + mi*16 + groupID;
            int gmB = gmA + 8;
            int gn0 = n0 + wn*32 + ni*8 + 2*tig;
            if (gmA < M) {
                if (gn0     < N) C[(size_t)gmA*N + gn0    ] = acc[mi][ni][0];
                if (gn0 + 1 < N) C[(size_t)gmA*N + gn0 + 1] = acc[mi][ni][1];
            }
            if (gmB < M) {
                if (gn0     < N) C[(size_t)gmB*N + gn0    ] = acc[mi][ni][2];
                if (gn0 + 1 < N) C[(size_t)gmB*N + gn0 + 1] = acc[mi][ni][3];
            }
        }
    }
}

// ---------------- tiled fp32 GEMM (64x64, small-M) ----------------
__global__ __launch_bounds__(128)
void gemm_kernel(const float* __restrict__ A, const float* __restrict__ B,
                 float* __restrict__ C, int M, int N, int K,
                 const float* __restrict__ bias, int reluOut, int reluA, int addC)
{
    __shared__ float As[64][17];
    __shared__ float Bs[16][64];
    int m0 = blockIdx.y * 64;
    int n0 = blockIdx.x * 64;
    int tid = threadIdx.x;
    int ty = tid >> 4;
    int tx = tid & 15;
    float acc[8][4];
#pragma unroll
    for (int i = 0; i < 8; i++)
#pragma unroll
        for (int j = 0; j < 4; j++) acc[i][j] = 0.f;

    for (int k0 = 0; k0 < K; k0 += 16) {
#pragma unroll
        for (int r = 0; r < 8; r++) {
            int t = tid + r*128;
            int m = t >> 4, k = t & 15;
            int gm = m0 + m, gk = k0 + k;
            float v = (gm < M && gk < K) ? A[(size_t)gm*K + gk] : 0.f;
            if (reluA) v = fmaxf(v, 0.f);
            As[m][k] = v;
        }
#pragma unroll
        for (int r = 0; r < 8; r++) {
            int t = tid + r*128;
            int k = t >> 6;
            int n = t & 63;
            int gk = k0 + k, gn = n0 + n;
            Bs[k][n] = (gk < K && gn < N) ? B[(size_t)gk*N + gn] : 0.f;
        }
        __syncthreads();
#pragma unroll
        for (int kk = 0; kk < 16; kk++) {
            float a[8], b[4];
#pragma unroll
            for (int i = 0; i < 8; i++) a[i] = As[ty*8 + i][kk];
#pragma unroll
            for (int j = 0; j < 4; j++) b[j] = Bs[kk][tx*4 + j];
#pragma unroll
            for (int i = 0; i < 8; i++)
#pragma unroll
                for (int j = 0; j < 4; j++) acc[i][j] = fmaf(a[i], b[j], acc[i][j]);
        }
        __syncthreads();
    }
#pragma unroll
    for (int i = 0; i < 8; i++) {
        int gm = m0 + ty*8 + i;
        if (gm >= M) continue;
#pragma unroll
        for (int j = 0; j < 4; j++) {
            int gn = n0 + tx*4 + j;
            if (gn >= N) continue;
            float v = acc[i][j];
            if (bias) v += bias[gn];
            if (addC) v += C[(size_t)gm*N + gn];
            if (reluOut) v = fmaxf(v, 0.f);
            C[(size_t)gm*N + gn] = v;
        }
    }
}

__global__ void reduce_splitk_kernel(const float* __restrict__ Cpart, float* __restrict__ C,
                                     int MN, int N, int S, const float* __restrict__ bias,
                                     int reluOut, int addC)
{
    int t = blockIdx.x * blockDim.x + threadIdx.x;
    if (t >= MN) return;
    float v = 0.f;
    for (int s = 0; s < S; s++) v += Cpart[(size_t)s*MN + t];
    if (bias) v += bias[t % N];
    if (addC) v += C[t];
    if (reluOut) v = fmaxf(v, 0.f);
    C[t] = v;
}

// ---------------- VQ ----------------
__global__ void vq_setup_kernel(const float* __restrict__ emb, float* __restrict__ esq,
                                int* __restrict__ counts, float* __restrict__ sqacc) {
    int k = threadIdx.x;
    float s = 0.f;
    const float* e = emb + k*64;
#pragma unroll
    for (int d = 0; d < 64; d++) s = fmaf(e[d], e[d], s);
    esq[k] = s;
    counts[k] = 0;
    if (k == 0) sqacc[0] = 0.f;
}

__global__ void vq_kernel(const float* __restrict__ z, const float* __restrict__ emb,
                          const float* __restrict__ esq, int* __restrict__ idx,
                          float* __restrict__ q, int* __restrict__ counts,
                          float* __restrict__ sqacc)
{
    __shared__ float zs[64];
    __shared__ float sb[128];
    __shared__ int   si[128];
    int pos = blockIdx.x;
    int tid = threadIdx.x;
    if (tid < 64) zs[tid] = z[pos*64 + tid];
    __syncthreads();
    float best = 3.4e38f; int bi = 0x7fffffff;
    for (int k = tid; k < KE; k += 128) {
        const float* e = emb + k*64;
        float dot = 0.f;
#pragma unroll
        for (int d = 0; d < 64; d++) dot = fmaf(e[d], zs[d], dot);
        float s = esq[k] - 2.f*dot;
        if (s < best || (s == best && k < bi)) { best = s; bi = k; }
    }
    sb[tid] = best; si[tid] = bi;
    __syncthreads();
    for (int off = 64; off > 0; off >>= 1) {
        if (tid < off) {
            float s2 = sb[tid+off]; int i2 = si[tid+off];
            if (s2 < sb[tid] || (s2 == sb[tid] && i2 < si[tid])) { sb[tid] = s2; si[tid] = i2; }
        }
        __syncthreads();
    }
    int bk = si[0];
    if (tid == 0) { idx[pos] = bk; atomicAdd(&counts[bk], 1); }
    __syncthreads();
    float v = 0.f;
    if (tid < 64) {
        float qv = emb[bk*64 + tid];
        q[pos*64 + tid] = qv;
        float d = qv - zs[tid];
        v = d*d;
    }
    sb[tid] = v;
    __syncthreads();
    for (int off = 64; off > 0; off >>= 1) {
        if (tid < off) sb[tid] += sb[tid+off];
        __syncthreads();
    }
    if (tid == 0) atomicAdd(sqacc, sb[0]);
}

__global__ void finalize_kernel(const int* __restrict__ counts, const float* __restrict__ sqacc,
                                float* __restrict__ out, long outN) {
    __shared__ float sh[512];
    int tid = threadIdx.x;
    float p = (float)counts[tid] / 960.f;
    sh[tid] = p * logf(p + 1e-10f);
    __syncthreads();
    for (int off = 256; off > 0; off >>= 1) {
        if (tid < off) sh[tid] += sh[tid+off];
        __syncthreads();
    }
    if (tid == 0) {
        out[0] = 1.25f * sqacc[0] / (float)(POS2*64);
        out[outN-1] = expf(-sh[0]);
    }
}

// ---------------- convT gathers ----------------
__global__ void gather_t1_kernel(const float* __restrict__ Y1, const float* __restrict__ bias,
                                 float* __restrict__ t1) {
    int t = blockIdx.x * blockDim.x + threadIdx.x;
    if (t >= POSD*16) return;
    int oc = (t & 15) * 4;
    int pos = t >> 4;
    int ow = pos % TW; int r = pos / TW;
    int oh = r % TH; int b = r / TH;
    float4 acc = *(const float4*)(bias + oc);
    int lo = oh - 10;
    int ih_lo = lo <= 0 ? 0 : (lo + 9)/10;
    int ih_hi = (oh + 1)/10; if (ih_hi > 4) ih_hi = 4;
    int lw = ow - 10;
    int iw_lo = lw <= 0 ? 0 : (lw + 9)/10;
    int iw_hi = (ow + 1)/10; if (iw_hi > 5) iw_hi = 5;
    for (int ih = ih_lo; ih <= ih_hi; ih++) {
        int kh = oh + 1 - 10*ih;
        for (int iw = iw_lo; iw <= iw_hi; iw++) {
            int kw = ow + 1 - 10*iw;
            float4 y = *(const float4*)(Y1 + (size_t)((b*5 + ih)*6 + iw)*NT1 + (kh*12 + kw)*64 + oc);
            acc.x += y.x; acc.y += y.y; acc.z += y.z; acc.w += y.w;
        }
    }
    acc.x = fmaxf(acc.x, 0.f); acc.y = fmaxf(acc.y, 0.f);
    acc.z = fmaxf(acc.z, 0.f); acc.w = fmaxf(acc.w, 0.f);
    *(float4*)(t1 + (size_t)pos*64 + oc) = acc;
}

__global__ void gather_recon_kernel(const float* __restrict__ Y2, const float* __restrict__ bias,
                                    float* __restrict__ out) {
    long t = (long)blockIdx.x * blockDim.x + threadIdx.x;
    if (t >= (long)RECON_N) return;
    int ow = (int)(t % OWW); long r = t / OWW;
    int oh = (int)(r % OHH); r /= OHH;
    int oc = (int)(r % 2); int b = (int)(r / 2);
    float acc = bias[oc];
    int lo = oh - 8;
    int ih_lo = lo <= 0 ? 0 : (lo + 7)/8;
    int ih_hi = (oh + 1)/8; if (ih_hi > 49) ih_hi = 49;
    int lw = ow - 9;
    int iw_lo = lw <= 0 ? 0 : (lw + 8)/9;
    int iw_hi = (ow + 1)/9; if (iw_hi > 59) iw_hi = 59;
    for (int ih = ih_lo; ih <= ih_hi; ih++) {
        int kh = oh + 1 - 8*ih;
        for (int iw = iw_lo; iw <= iw_hi; iw++) {
            int kw = ow + 1 - 9*iw;
            acc += Y2[(size_t)((b*TH + ih)*TW + iw)*NT2 + (kh*11 + kw)*2 + oc];
        }
    }
    out[t] = acc;
}

// ---------------- host ----------------
static inline void launch_gemm3x_splitk(const float* A, const float* B, float* C, float* part,
                                        int M, int N, int K, int S, const float* bias,
                                        int reluOut, int reluA, int addC) {
    int Kc = (K + S - 1) / S;
    Kc = ((Kc + 15) / 16) * 16;
    S  = (K + Kc - 1) / Kc;
    dim3 grid((N + 63)/64, (M + 127)/128, S);
    gemm3x_kernel<<<grid, 256>>>(A, B, part, M, N, K, Kc, 0, 0, reluA);
    int MN = M * N;
    reduce_splitk_kernel<<<(MN + 255)/256, 256>>>(part, C, MN, N, S, bias, reluOut, addC);
}

static inline void launch_gemm_tf32(const float* A, const float* B, float* C,
                                    int M, int N, int K, int reluA) {
    dim3 grid((N + 63)/64, (M + 127)/128);
    gemm_tf32_kernel<<<grid, 256>>>(A, B, C, M, N, K, reluA);
}

static inline void launch_gemm(const float* A, const float* B, float* C,
                               int M, int N, int K, const float* bias,
                               int reluOut, int reluA, int addC) {
    dim3 grid((N + 63)/64, (M + 63)/64);
    gemm_kernel<<<grid, 128>>>(A, B, C, M, N, K, bias, reluOut, reluA, addC);
}

template<int H,int W,int C,int KH,int KW,int SH,int SW,int OH,int OW,int RELU>
static inline void launch_im2col4(const float* in, float* out) {
    int total4 = NB*OH*OW*KH*KW*(C/4);
    im2col4_kernel<H,W,C,KH,KW,SH,SW,OH,OW,RELU><<<(total4+255)/256, 256>>>(in, out, total4);
}

extern "C" void kernel_launch(void* const* d_in, const int* in_sizes, int n_in,
                              void* d_out, int out_size) {
    const float* x       = (const float*)d_in[0];
    const float* enc_w1  = (const float*)d_in[1];
    const float* enc_b1  = (const float*)d_in[2];
    const float* enc_w2  = (const float*)d_in[3];
    const float* enc_b2  = (const float*)d_in[4];
    const float* enc_w3  = (const float*)d_in[5];
    const float* enc_b3  = (const float*)d_in[6];
    const float* enc_rw1 = (const float*)d_in[7];
    const float* enc_rw2 = (const float*)d_in[8];
    const float* pre_w   = (const float*)d_in[9];
    const float* pre_b   = (const float*)d_in[10];
    const float* emb     = (const float*)d_in[11];
    const float* dec_w1  = (const float*)d_in[12];
    const float* dec_b1  = (const float*)d_in[13];
    const float* dec_rw1 = (const float*)d_in[14];
    const float* dec_rw2 = (const float*)d_in[15];
    const float* dec_tw1 = (const float*)d_in[16];
    const float* dec_tb1 = (const float*)d_in[17];
    const float* dec_tw2 = (const float*)d_in[18];
    const float* dec_tb2 = (const float*)d_in[19];
    float* out = (float*)d_out;

    float *p_h1, *p_col, *p_hA, *p_hB, *p_t64, *p_z, *p_q, *p_part;
    float *p_Y1, *p_t1, *p_Y2;
    float *p_w1t, *p_w2t, *p_w3t, *p_er1t, *p_er2t, *p_pret, *p_d1t, *p_dr1t, *p_dr2t;
    float *p_tw1t, *p_tw2t, *p_esq, *p_sqacc;
    int *p_counts, *p_idx;
    cudaGetSymbolAddress((void**)&p_h1, g_h1);
    cudaGetSymbolAddress((void**)&p_col, g_col);
    cudaGetSymbolAddress((void**)&p_hA, g_hA);
    cudaGetSymbolAddress((void**)&p_hB, g_hB);
    cudaGetSymbolAddress((void**)&p_t64, g_t64);
    cudaGetSymbolAddress((void**)&p_z, g_z);
    cudaGetSymbolAddress((void**)&p_q, g_q);
    cudaGetSymbolAddress((void**)&p_part, g_part);
    cudaGetSymbolAddress((void**)&p_Y1, g_Y1);
    cudaGetSymbolAddress((void**)&p_t1, g_t1);
    cudaGetSymbolAddress((void**)&p_Y2, g_Y2);
    cudaGetSymbolAddress((void**)&p_w1t, g_w1t);
    cudaGetSymbolAddress((void**)&p_w2t, g_w2t);
    cudaGetSymbolAddress((void**)&p_w3t, g_w3t);
    cudaGetSymbolAddress((void**)&p_er1t, g_er1t);
    cudaGetSymbolAddress((void**)&p_er2t, g_er2t);
    cudaGetSymbolAddress((void**)&p_pret, g_pret);
    cudaGetSymbolAddress((void**)&p_d1t, g_d1t);
    cudaGetSymbolAddress((void**)&p_dr1t, g_dr1t);
    cudaGetSymbolAddress((void**)&p_dr2t, g_dr2t);
    cudaGetSymbolAddress((void**)&p_tw1t, g_tw1t);
    cudaGetSymbolAddress((void**)&p_tw2t, g_tw2t);
    cudaGetSymbolAddress((void**)&p_esq, g_esq);
    cudaGetSymbolAddress((void**)&p_sqacc, g_sqacc);
    cudaGetSymbolAddress((void**)&p_counts, g_counts);
    cudaGetSymbolAddress((void**)&p_idx, g_idx);

    // ---- ONE merged weight-transpose kernel ----
    {
        TJobs J;
        int j = 0;
        long off = 0;
        auto add = [&](const float* s, float* d, int co, int ci, int kh, int kw, int isT) {
            J.src[j] = s; J.dst[j] = d;
            J.cout[j] = co; J.cin[j] = ci; J.kh[j] = kh; J.kw[j] = kw; J.isT[j] = isT;
            J.off[j] = off;
            off += (long)co*ci*kh*kw;
            j++;
        };
        add(enc_w1,            p_w1t,            64, 2,  10, 11, 0);
        add(enc_w2,            p_w2t,            128,64, 12, 12, 0);
        add(enc_w3,            p_w3t,            128,128, 3,  3, 0);
        add(enc_rw1,           p_er1t,            64,128, 3,  3, 0);
        add(enc_rw1 + 73728,   p_er1t + 73728,    64,128, 3,  3, 0);
        add(enc_rw2,           p_er2t,           128, 64, 1,  1, 0);
        add(enc_rw2 + 8192,    p_er2t + 8192,    128, 64, 1,  1, 0);
        add(pre_w,             p_pret,            64,128, 1,  1, 0);
        add(dec_w1,            p_d1t,            128, 64, 3,  3, 0);
        add(dec_rw1,           p_dr1t,            64,128, 3,  3, 0);
        add(dec_rw1 + 73728,   p_dr1t + 73728,    64,128, 3,  3, 0);
        add(dec_rw2,           p_dr2t,           128, 64, 1,  1, 0);
        add(dec_rw2 + 8192,    p_dr2t + 8192,    128, 64, 1,  1, 0);
        add(dec_tw1,           p_tw1t,            64,128, 12, 12, 1);
        add(dec_tw2,           p_tw2t,             2, 64, 10, 11, 1);
        J.off[NJOBS] = off;
        long blocks = (off + 255)/256;
        wtrans_all_kernel<<<(unsigned)blocks, 256>>>(J);
    }

    // ---- encoder (fp32-accurate; safe for VQ argmin) ----
    // conv1: implicit GEMM (im2col fused into A-loader), +bias +relu
    {
        dim3 grid(1, (POS1 + 127)/128);
        conv1_kernel<<<grid, 128>>>(x, p_w1t, p_h1, enc_b1);
    }

    launch_im2col4<H1,W1,64,12,12,10,10,H2,W2,0>(p_h1, p_col);
    launch_gemm3x_splitk(p_col, p_w2t, p_hA, p_part, POS2, 128, K2, 8, enc_b2, 1, 0, 0);

    launch_im2col4<H2,W2,128,3,3,1,1,H2,W2,0>(p_hA, p_col);
    launch_gemm3x_splitk(p_col, p_w3t, p_hB, p_part, POS2, 128, 1152, 8, enc_b3, 0, 0, 0);

    for (int i = 0; i < 2; i++) {
        launch_im2col4<H2,W2,128,3,3,1,1,H2,W2,1>(p_hB, p_col);
        launch_gemm3x_splitk(p_col, p_er1t + i*1152*64, p_t64, p_part, POS2, 64, 1152, 8, 0, 1, 0, 0);
        launch_gemm(p_t64, p_er2t + i*64*128, p_hB, POS2, 128, 64, 0, 0, 0, 1);
    }
    launch_gemm(p_hB, p_pret, p_z, POS2, 64, 128, pre_b, 0, 1, 0);

    // ---- VQ ----
    vq_setup_kernel<<<1, KE>>>(emb, p_esq, p_counts, p_sqacc);
    vq_kernel<<<POS2, 128>>>(p_z, emb, p_esq, p_idx, p_q, p_counts, p_sqacc);
    finalize_kernel<<<1, KE>>>(p_counts, p_sqacc, out, (long)out_size);

    // ---- decoder ----
    launch_im2col4<H2,W2,64,3,3,1,1,H2,W2,0>(p_q, p_col);
    launch_gemm3x_splitk(p_col, p_d1t, p_hA, p_part, POS2, 128, 576, 4, dec_b1, 0, 0, 0);

    for (int i = 0; i < 2; i++) {
        launch_im2col4<H2,W2,128,3,3,1,1,H2,W2,1>(p_hA, p_col);
        launch_gemm3x_splitk(p_col, p_dr1t + i*1152*64, p_t64, p_part, POS2, 64, 1152, 8, 0, 1, 0, 0);
        launch_gemm(p_t64, p_dr2t + i*64*128, p_hA, POS2, 128, 64, 0, 0, 0, 1);
    }

    // convT1: tf32 GEMM (relu on input) + gather (+bias, relu)
    launch_gemm_tf32(p_hA, p_tw1t, p_Y1, POS2, NT1, 128, 1);
    gather_t1_kernel<<<(POSD*16 + 255)/256, 256>>>(p_Y1, dec_tb1, p_t1);

    // convT2: tf32 GEMM + gather (+bias) -> recon at out+1
    launch_gemm_tf32(p_t1, p_tw2t, p_Y2, POSD, NT2, 64, 0);
    {
        long tot = (long)RECON_N;
        gather_recon_kernel<<<(unsigned)((tot+255)/256), 256>>>(p_Y2, dec_tb2, out + 1);
    }
}

// round 12
// speedup vs baseline: 1.2334x; 1.2334x over previous
#include <cuda_runtime.h>
#include <math.h>
#include <stdint.h>

// ---------------- dimensions ----------------
#define NB   32
#define C0   2
#define H0   400
#define W0   600
#define KH1  10
#define KW1  11
#define H1   50
#define W1   66
#define OC1  64
#define POS1 (NB*H1*W1)          // 105600
#define K1   (KH1*KW1*C0)        // 220
#define H2   5
#define W2   6
#define POS2 (NB*H2*W2)          // 960
#define K2   (12*12*64)          // 9216
#define KE   512
#define TH   50
#define TW   60
#define POSD (NB*TH*TW)          // 96000
#define NT1  (12*12*64)          // 9216
#define NT2  (10*11*2)           // 220
#define OHH  400
#define OWW  540
#define RECON_N (NB*2*OHH*OWW)   // 13824000

// ---------------- scratch ----------------
__device__ float g_A1  [(size_t)POS1*K1];
__device__ float g_h1  [(size_t)POS1*OC1];
__device__ float g_col [(size_t)POS2*K2];
__device__ float g_hA  [POS2*128];
__device__ float g_hB  [POS2*128];
__device__ float g_t64 [POS2*64];
__device__ float g_z   [POS2*64];
__device__ float g_q   [POS2*64];
__device__ float g_part[16*POS2*128];
__device__ float g_Y1  [(size_t)POS2*NT1];
__device__ float g_t1  [(size_t)POSD*64];
__device__ float g_Y2  [(size_t)POSD*NT2];
__device__ float g_w1t [K1*OC1];
__device__ float g_w2t [K2*128];
__device__ float g_w3t [9*128*128];
__device__ float g_er1t[2*9*128*64];
__device__ float g_er2t[2*64*128];
__device__ float g_pret[128*64];
__device__ float g_d1t [9*64*128];
__device__ float g_dr1t[2*9*128*64];
__device__ float g_dr2t[2*64*128];
__device__ float g_tw1t[128*NT1];
__device__ float g_tw2t[64*NT2];
__device__ float g_esq [KE];
__device__ int   g_counts[KE];
__device__ float g_sqacc[1];
__device__ int   g_idx [POS2];

// ---------------- merged weight transpose ----------------
#define NJOBS 15
struct TJobs {
    const float* src[NJOBS];
    float*       dst[NJOBS];
    int cout[NJOBS], cin[NJOBS], kh[NJOBS], kw[NJOBS], isT[NJOBS];
    long off[NJOBS+1];
};

__global__ void wtrans_all_kernel(TJobs J) {
    long t = (long)blockIdx.x * blockDim.x + threadIdx.x;
    if (t >= J.off[NJOBS]) return;
    int j = 0;
#pragma unroll
    for (int i = 0; i < NJOBS-1; i++) j += (t >= J.off[i+1]) ? 1 : 0;
    long u = t - J.off[j];
    int Cout = J.cout[j], Cin = J.cin[j], KH = J.kh[j], KW = J.kw[j];
    int oc = (int)(u % Cout); long r = u / Cout;
    if (!J.isT[j]) {
        int ic = (int)(r % Cin);
        int kk = (int)(r / Cin);
        int khh = kk / KW, kww = kk % KW;
        J.dst[j][u] = J.src[j][((oc*Cin + ic)*KH + khh)*KW + kww];
    } else {
        int khw = KH*KW;
        int kk = (int)(r % khw);
        int ic = (int)(r / khw);
        J.dst[j][u] = J.src[j][(ic*Cout + oc)*khw + kk];
    }
}

// ---------------- conv1 im2col: NCHW in, C0=2, float2 store ----------------
__global__ void im2col_c1_kernel(const float* __restrict__ in, float* __restrict__ out) {
    const int total2 = POS1 * (K1/2);
    int t = blockIdx.x * blockDim.x + threadIdx.x;
    if (t >= total2) return;
    int k2  = t % 110;
    int pos = t / 110;
    int kw = k2 % 11;
    int kh = k2 / 11;
    int ow = pos % W1;
    int r2 = pos / W1;
    int oh = r2 % H1;
    int b  = r2 / H1;
    int ih = oh*8 - 1 + kh;
    int iw = ow*9 - 1 + kw;
    float v0 = 0.f, v1 = 0.f;
    if (ih >= 0 && ih < H0 && iw >= 0 && iw < W0) {
        long base = (((long)b*2)*H0 + ih)*W0 + iw;
        v0 = in[base];
        v1 = in[base + (long)H0*W0];
    }
    *(float2*)(out + (size_t)t*2) = make_float2(v0, v1);
}

// ---------------- templated NHWC im2col, 4 channels per thread ----------------
template<int H,int W,int C,int KH,int KW,int SH,int SW,int OH,int OW,int RELU>
__global__ void im2col4_kernel(const float* __restrict__ in, float* __restrict__ out, int total4) {
    int t = blockIdx.x * blockDim.x + threadIdx.x;
    if (t >= total4) return;
    constexpr int KC4 = KH*KW*(C/4);
    int k4  = t % KC4;
    int pos = t / KC4;
    int ic = (k4 % (C/4)) * 4;
    int r  = k4 / (C/4);
    int kw = r % KW;
    int kh = r / KW;
    int ow = pos % OW;
    int r2 = pos / OW;
    int oh = r2 % OH;
    int b  = r2 / OH;
    int ih = oh*SH - 1 + kh;
    int iw = ow*SW - 1 + kw;
    float4 v = make_float4(0.f, 0.f, 0.f, 0.f);
    if (ih >= 0 && ih < H && iw >= 0 && iw < W) {
        v = *(const float4*)(in + (((long)(b*H + ih))*W + iw)*C + ic);
        if (RELU) {
            v.x = fmaxf(v.x, 0.f); v.y = fmaxf(v.y, 0.f);
            v.z = fmaxf(v.z, 0.f); v.w = fmaxf(v.w, 0.f);
        }
    }
    *(float4*)(out + (size_t)t*4) = v;
}

// ---------------- tf32 helpers ----------------
__device__ __forceinline__ uint32_t f2tf32(float x) {
    uint32_t r;
    asm("cvt.rna.tf32.f32 %0, %1;" : "=r"(r) : "f"(x));
    return r;
}
__device__ __forceinline__ void split3(float v, uint32_t& hi, uint32_t& lo) {
    hi = f2tf32(v);
    lo = f2tf32(v - __uint_as_float(hi));
}
#define MMA_TF32(acc, a0,a1,a2,a3, b0,b1) \
    asm volatile( \
        "mma.sync.aligned.m16n8k8.row.col.f32.tf32.tf32.f32 " \
        "{%0,%1,%2,%3}, {%4,%5,%6,%7}, {%8,%9}, {%0,%1,%2,%3};" \
        : "+f"((acc)[0]), "+f"((acc)[1]), "+f"((acc)[2]), "+f"((acc)[3]) \
        : "r"(a0), "r"(a1), "r"(a2), "r"(a3), "r"(b0), "r"(b1))

// ---------------- 3xTF32 GEMM (fp32-accurate, tensor cores; split-K) ----------------
__global__ __launch_bounds__(256)
void gemm3x_kernel(const float* __restrict__ A, const float* __restrict__ B,
                   float* __restrict__ C, int M, int N, int K, int Kc,
                   const float* __restrict__ bias, int reluOut, int reluA)
{
    __shared__ float As[128][17];
    __shared__ float Bs[16][72];
    int m0 = blockIdx.y * 128;
    int n0 = blockIdx.x * 64;
    int s  = blockIdx.z;
    int kbeg = s * Kc;
    int kend = kbeg + Kc; if (kend > K) kend = K;
    int tid = threadIdx.x;
    int warp = tid >> 5, lane = tid & 31;
    int wm = warp >> 1, wn = warp & 1;
    int g = lane >> 2, tg = lane & 3;

    float acc[2][4][4];
#pragma unroll
    for (int mi = 0; mi < 2; mi++)
#pragma unroll
        for (int ni = 0; ni < 4; ni++)
#pragma unroll
            for (int c = 0; c < 4; c++) acc[mi][ni][c] = 0.f;

    for (int k0 = kbeg; k0 < kend; k0 += 16) {
#pragma unroll
        for (int r = 0; r < 8; r++) {
            int t = tid + r*256;
            int m = t >> 4, k = t & 15;
            int gm = m0 + m, gk = k0 + k;
            float v = (gm < M && gk < kend) ? A[(size_t)gm*K + gk] : 0.f;
            if (reluA) v = fmaxf(v, 0.f);
            As[m][k] = v;
        }
#pragma unroll
        for (int r = 0; r < 4; r++) {
            int t = tid + r*256;
            int k = t >> 6, n = t & 63;
            int gk = k0 + k, gn = n0 + n;
            Bs[k][n] = (gk < kend && gn < N) ? B[(size_t)gk*N + gn] : 0.f;
        }
        __syncthreads();
#pragma unroll
        for (int kk = 0; kk < 16; kk += 8) {
            uint32_t ah[2][4], al[2][4], bh[4][2], bl[4][2];
#pragma unroll
            for (int mi = 0; mi < 2; mi++) {
                int mrow = wm*32 + mi*16;
                split3(As[mrow + g    ][kk + tg    ], ah[mi][0], al[mi][0]);
                split3(As[mrow + g + 8][kk + tg    ], ah[mi][1], al[mi][1]);
                split3(As[mrow + g    ][kk + tg + 4], ah[mi][2], al[mi][2]);
                split3(As[mrow + g + 8][kk + tg + 4], ah[mi][3], al[mi][3]);
            }
#pragma unroll
            for (int ni = 0; ni < 4; ni++) {
                int ncol = wn*32 + ni*8 + g;
                split3(Bs[kk + tg    ][ncol], bh[ni][0], bl[ni][0]);
                split3(Bs[kk + tg + 4][ncol], bh[ni][1], bl[ni][1]);
            }
#pragma unroll
            for (int mi = 0; mi < 2; mi++)
#pragma unroll
                for (int ni = 0; ni < 4; ni++) {
                    MMA_TF32(acc[mi][ni], ah[mi][0],ah[mi][1],ah[mi][2],ah[mi][3], bl[ni][0],bl[ni][1]);
                    MMA_TF32(acc[mi][ni], al[mi][0],al[mi][1],al[mi][2],al[mi][3], bh[ni][0],bh[ni][1]);
                    MMA_TF32(acc[mi][ni], ah[mi][0],ah[mi][1],ah[mi][2],ah[mi][3], bh[ni][0],bh[ni][1]);
                }
        }
        __syncthreads();
    }
    int splitk = (gridDim.z > 1);
    float* Cs = splitk ? (C + (size_t)s*M*N) : C;
#pragma unroll
    for (int mi = 0; mi < 2; mi++) {
#pragma unroll
        for (int ni = 0; ni < 4; ni++) {
            int gmA = m0 + wm*32 + mi*16 + g;
            int gmB = gmA + 8;
            int gn0 = n0 + wn*32 + ni*8 + 2*tg;
            float v0 = acc[mi][ni][0], v1 = acc[mi][ni][1];
            float v2 = acc[mi][ni][2], v3 = acc[mi][ni][3];
            if (!splitk) {
                if (bias) {
                    float b0 = (gn0 < N) ? bias[gn0] : 0.f;
                    float b1 = (gn0+1 < N) ? bias[gn0+1] : 0.f;
                    v0 += b0; v1 += b1; v2 += b0; v3 += b1;
                }
                if (reluOut) {
                    v0 = fmaxf(v0, 0.f); v1 = fmaxf(v1, 0.f);
                    v2 = fmaxf(v2, 0.f); v3 = fmaxf(v3, 0.f);
                }
            }
            if (gmA < M) {
                if (gn0     < N) Cs[(size_t)gmA*N + gn0    ] = v0;
                if (gn0 + 1 < N) Cs[(size_t)gmA*N + gn0 + 1] = v1;
            }
            if (gmB < M) {
                if (gn0     < N) Cs[(size_t)gmB*N + gn0    ] = v2;
                if (gn0 + 1 < N) Cs[(size_t)gmB*N + gn0 + 1] = v3;
            }
        }
    }
}

// ---------------- plain tf32 GEMM (decoder only) ----------------
__global__ __launch_bounds__(256)
void gemm_tf32_kernel(const float* __restrict__ A, const float* __restrict__ B,
                      float* __restrict__ C, int M, int N, int K, int reluA)
{
    __shared__ uint32_t As[128][17];
    __shared__ uint32_t Bs[16][72];
    int m0 = blockIdx.y * 128;
    int n0 = blockIdx.x * 64;
    int tid = threadIdx.x;
    int warp = tid >> 5, lane = tid & 31;
    int wm = warp >> 1, wn = warp & 1;
    int groupID = lane >> 2, tig = lane & 3;

    float acc[2][4][4];
#pragma unroll
    for (int mi = 0; mi < 2; mi++)
#pragma unroll
        for (int ni = 0; ni < 4; ni++)
#pragma unroll
            for (int c = 0; c < 4; c++) acc[mi][ni][c] = 0.f;

    for (int k0 = 0; k0 < K; k0 += 16) {
#pragma unroll
        for (int r = 0; r < 8; r++) {
            int t = tid + r*256;
            int m = t >> 4, k = t & 15;
            int gm = m0 + m, gk = k0 + k;
            float v = (gm < M && gk < K) ? A[(size_t)gm*K + gk] : 0.f;
            if (reluA) v = fmaxf(v, 0.f);
            As[m][k] = f2tf32(v);
        }
#pragma unroll
        for (int r = 0; r < 4; r++) {
            int t = tid + r*256;
            int k = t >> 6, n = t & 63;
            int gk = k0 + k, gn = n0 + n;
            float v = (gk < K && gn < N) ? B[(size_t)gk*N + gn] : 0.f;
            Bs[k][n] = f2tf32(v);
        }
        __syncthreads();
#pragma unroll
        for (int kk = 0; kk < 16; kk += 8) {
            uint32_t a[2][4], b[4][2];
#pragma unroll
            for (int mi = 0; mi < 2; mi++) {
                int mrow = wm*32 + mi*16;
                a[mi][0] = As[mrow + groupID    ][kk + tig    ];
                a[mi][1] = As[mrow + groupID + 8][kk + tig    ];
                a[mi][2] = As[mrow + groupID    ][kk + tig + 4];
                a[mi][3] = As[mrow + groupID + 8][kk + tig + 4];
            }
#pragma unroll
            for (int ni = 0; ni < 4; ni++) {
                int ncol = wn*32 + ni*8 + groupID;
                b[ni][0] = Bs[kk + tig    ][ncol];
                b[ni][1] = Bs[kk + tig + 4][ncol];
            }
#pragma unroll
            for (int mi = 0; mi < 2; mi++)
#pragma unroll
                for (int ni = 0; ni < 4; ni++)
                    MMA_TF32(acc[mi][ni], a[mi][0],a[mi][1],a[mi][2],a[mi][3], b[ni][0],b[ni][1]);
        }
        __syncthreads();
    }
#pragma unroll
    for (int mi = 0; mi < 2; mi++) {
#pragma unroll
        for (int ni = 0; ni < 4; ni++) {
            int gmA = m0 + wm*32 + mi*16 + groupID;
            int gmB = gmA + 8;
            int gn0 = n0 + wn*32 + ni*8 + 2*tig;
            if (gmA < M) {
                if (gn0     < N) C[(size_t)gmA*N + gn0    ] = acc[mi][ni][0];
                if (gn0 + 1 < N) C[(size_t)gmA*N + gn0 + 1] = acc[mi][ni][1];
            }
            if (gmB < M) {
                if (gn0     < N) C[(size_t)gmB*N + gn0    ] = acc[mi][ni][2];
                if (gn0 + 1 < N) C[(size_t)gmB*N + gn0 + 1] = acc[mi][ni][3];
            }
        }
    }
}

// ---------------- gemm128: 128x64 tile, 8x8 micro, 128 threads (conv1) ----------------
__global__ __launch_bounds__(128)
void gemm128_kernel(const float* __restrict__ A, const float* __restrict__ B,
                    float* __restrict__ C, int M, int N, int K,
                    const float* __restrict__ bias, int reluOut, int reluA)
{
    __shared__ float As[128][17];
    __shared__ float Bs[16][64];
    int m0 = blockIdx.y * 128;
    int n0 = blockIdx.x * 64;
    int tid = threadIdx.x;
    int tym = tid >> 3;
    int txn = tid & 7;
    float acc[8][8];
#pragma unroll
    for (int i = 0; i < 8; i++)
#pragma unroll
        for (int j = 0; j < 8; j++) acc[i][j] = 0.f;

    for (int k0 = 0; k0 < K; k0 += 16) {
#pragma unroll
        for (int r = 0; r < 16; r++) {
            int t = tid + r*128;
            int m = t >> 4, k = t & 15;
            int gm = m0 + m, gk = k0 + k;
            float v = (gm < M && gk < K) ? A[(size_t)gm*K + gk] : 0.f;
            if (reluA) v = fmaxf(v, 0.f);
            As[m][k] = v;
        }
        {
            int n = tid & 63;
            int kb = tid >> 6;
#pragma unroll
            for (int r = 0; r < 8; r++) {
                int k = kb + r*2;
                int gk = k0 + k, gn = n0 + n;
                Bs[k][n] = (gk < K && gn < N) ? B[(size_t)gk*N + gn] : 0.f;
            }
        }
        __syncthreads();
#pragma unroll
        for (int kk = 0; kk < 16; kk++) {
            float a[8], b[8];
#pragma unroll
            for (int i = 0; i < 8; i++) a[i] = As[tym*8 + i][kk];
            float4 b0 = *(const float4*)&Bs[kk][txn*8];
            float4 b1 = *(const float4*)&Bs[kk][txn*8 + 4];
            b[0]=b0.x; b[1]=b0.y; b[2]=b0.z; b[3]=b0.w;
            b[4]=b1.x; b[5]=b1.y; b[6]=b1.z; b[7]=b1.w;
#pragma unroll
            for (int i = 0; i < 8; i++)
#pragma unroll
                for (int j = 0; j < 8; j++)
                    acc[i][j] = fmaf(a[i], b[j], acc[i][j]);
        }
        __syncthreads();
    }
#pragma unroll
    for (int i = 0; i < 8; i++) {
        int gm = m0 + tym*8 + i;
        if (gm >= M) continue;
#pragma unroll
        for (int j = 0; j < 8; j++) {
            int gn = n0 + txn*8 + j;
            if (gn >= N) continue;
            float v = acc[i][j];
            if (bias) v += bias[gn];
            if (reluOut) v = fmaxf(v, 0.f);
            C[(size_t)gm*N + gn] = v;
        }
    }
}

// ---------------- tiled fp32 GEMM (64x64, small-M) ----------------
__global__ __launch_bounds__(128)
void gemm_kernel(const float* __restrict__ A, const float* __restrict__ B,
                 float* __restrict__ C, int M, int N, int K,
                 const float* __restrict__ bias, int reluOut, int reluA, int addC)
{
    __shared__ float As[64][17];
    __shared__ float Bs[16][64];
    int m0 = blockIdx.y * 64;
    int n0 = blockIdx.x * 64;
    int tid = threadIdx.x;
    int ty = tid >> 4;
    int tx = tid & 15;
    float acc[8][4];
#pragma unroll
    for (int i = 0; i < 8; i++)
#pragma unroll
        for (int j = 0; j < 4; j++) acc[i][j] = 0.f;

    for (int k0 = 0; k0 < K; k0 += 16) {
#pragma unroll
        for (int r = 0; r < 8; r++) {
            int t = tid + r*128;
            int m = t >> 4, k = t & 15;
            int gm = m0 + m, gk = k0 + k;
            float v = (gm < M && gk < K) ? A[(size_t)gm*K + gk] : 0.f;
            if (reluA) v = fmaxf(v, 0.f);
            As[m][k] = v;
        }
#pragma unroll
        for (int r = 0; r < 8; r++) {
            int t = tid + r*128;
            int k = t >> 6;
            int n = t & 63;
            int gk = k0 + k, gn = n0 + n;
            Bs[k][n] = (gk < K && gn < N) ? B[(size_t)gk*N + gn] : 0.f;
        }
        __syncthreads();
#pragma unroll
        for (int kk = 0; kk < 16; kk++) {
            float a[8], b[4];
#pragma unroll
            for (int i = 0; i < 8; i++) a[i] = As[ty*8 + i][kk];
#pragma unroll
            for (int j = 0; j < 4; j++) b[j] = Bs[kk][tx*4 + j];
#pragma unroll
            for (int i = 0; i < 8; i++)
#pragma unroll
                for (int j = 0; j < 4; j++) acc[i][j] = fmaf(a[i], b[j], acc[i][j]);
        }
        __syncthreads();
    }
#pragma unroll
    for (int i = 0; i < 8; i++) {
        int gm = m0 + ty*8 + i;
        if (gm >= M) continue;
#pragma unroll
        for (int j = 0; j < 4; j++) {
            int gn = n0 + tx*4 + j;
            if (gn >= N) continue;
            float v = acc[i][j];
            if (bias) v += bias[gn];
            if (addC) v += C[(size_t)gm*N + gn];
            if (reluOut) v = fmaxf(v, 0.f);
            C[(size_t)gm*N + gn] = v;
        }
    }
}

// ---------------- fp32 split-K GEMM (64x64) ----------------
__global__ __launch_bounds__(128)
void gemm_splitk_kernel(const float* __restrict__ A, const float* __restrict__ B,
                        float* __restrict__ Cpart, int M, int N, int K, int Kc)
{
    __shared__ float As[64][17];
    __shared__ float Bs[16][64];
    int m0 = blockIdx.y * 64;
    int n0 = blockIdx.x * 64;
    int s  = blockIdx.z;
    int kbeg = s * Kc;
    int kend = kbeg + Kc; if (kend > K) kend = K;
    int tid = threadIdx.x;
    int ty = tid >> 4;
    int tx = tid & 15;
    float acc[8][4];
#pragma unroll
    for (int i = 0; i < 8; i++)
#pragma unroll
        for (int j = 0; j < 4; j++) acc[i][j] = 0.f;

    for (int k0 = kbeg; k0 < kend; k0 += 16) {
#pragma unroll
        for (int r = 0; r < 8; r++) {
            int t = tid + r*128;
            int m = t >> 4, k = t & 15;
            int gm = m0 + m, gk = k0 + k;
            As[m][k] = (gm < M && gk < kend) ? A[(size_t)gm*K + gk] : 0.f;
        }
#pragma unroll
        for (int r = 0; r < 8; r++) {
            int t = tid + r*128;
            int k = t >> 6;
            int n = t & 63;
            int gk = k0 + k, gn = n0 + n;
            Bs[k][n] = (gk < kend && gn < N) ? B[(size_t)gk*N + gn] : 0.f;
        }
        __syncthreads();
#pragma unroll
        for (int kk = 0; kk < 16; kk++) {
            float a[8], b[4];
#pragma unroll
            for (int i = 0; i < 8; i++) a[i] = As[ty*8 + i][kk];
#pragma unroll
            for (int j = 0; j < 4; j++) b[j] = Bs[kk][tx*4 + j];
#pragma unroll
            for (int i = 0; i < 8; i++)
#pragma unroll
                for (int j = 0; j < 4; j++) acc[i][j] = fmaf(a[i], b[j], acc[i][j]);
        }
        __syncthreads();
    }
    float* Cs = Cpart + (size_t)s * M * N;
#pragma unroll
    for (int i = 0; i < 8; i++) {
        int gm = m0 + ty*8 + i;
        if (gm >= M) continue;
#pragma unroll
        for (int j = 0; j < 4; j++) {
            int gn = n0 + tx*4 + j;
            if (gn >= N) continue;
            Cs[(size_t)gm*N + gn] = acc[i][j];
        }
    }
}

__global__ void reduce_splitk_kernel(const float* __restrict__ Cpart, float* __restrict__ C,
                                     int MN, int N, int S, const float* __restrict__ bias,
                                     int reluOut, int addC)
{
    int t = blockIdx.x * blockDim.x + threadIdx.x;
    if (t >= MN) return;
    float v = 0.f;
    for (int s = 0; s < S; s++) v += Cpart[(size_t)s*MN + t];
    if (bias) v += bias[t % N];
    if (addC) v += C[t];
    if (reluOut) v = fmaxf(v, 0.f);
    C[t] = v;
}

// ---------------- VQ ----------------
__global__ void vq_setup_kernel(const float* __restrict__ emb, float* __restrict__ esq,
                                int* __restrict__ counts, float* __restrict__ sqacc) {
    int k = threadIdx.x;
    float s = 0.f;
    const float* e = emb + k*64;
#pragma unroll
    for (int d = 0; d < 64; d++) s = fmaf(e[d], e[d], s);
    esq[k] = s;
    counts[k] = 0;
    if (k == 0) sqacc[0] = 0.f;
}

__global__ void vq_kernel(const float* __restrict__ z, const float* __restrict__ emb,
                          const float* __restrict__ esq, int* __restrict__ idx,
                          float* __restrict__ q, int* __restrict__ counts,
                          float* __restrict__ sqacc)
{
    __shared__ float zs[64];
    __shared__ float sb[128];
    __shared__ int   si[128];
    int pos = blockIdx.x;
    int tid = threadIdx.x;
    if (tid < 64) zs[tid] = z[pos*64 + tid];
    __syncthreads();
    float best = 3.4e38f; int bi = 0x7fffffff;
    for (int k = tid; k < KE; k += 128) {
        const float* e = emb + k*64;
        float dot = 0.f;
#pragma unroll
        for (int d = 0; d < 64; d++) dot = fmaf(e[d], zs[d], dot);
        float s = esq[k] - 2.f*dot;
        if (s < best || (s == best && k < bi)) { best = s; bi = k; }
    }
    sb[tid] = best; si[tid] = bi;
    __syncthreads();
    for (int off = 64; off > 0; off >>= 1) {
        if (tid < off) {
            float s2 = sb[tid+off]; int i2 = si[tid+off];
            if (s2 < sb[tid] || (s2 == sb[tid] && i2 < si[tid])) { sb[tid] = s2; si[tid] = i2; }
        }
        __syncthreads();
    }
    int bk = si[0];
    if (tid == 0) { idx[pos] = bk; atomicAdd(&counts[bk], 1); }
    __syncthreads();
    float v = 0.f;
    if (tid < 64) {
        float qv = emb[bk*64 + tid];
        q[pos*64 + tid] = qv;
        float d = qv - zs[tid];
        v = d*d;
    }
    sb[tid] = v;
    __syncthreads();
    for (int off = 64; off > 0; off >>= 1) {
        if (tid < off) sb[tid] += sb[tid+off];
        __syncthreads();
    }
    if (tid == 0) atomicAdd(sqacc, sb[0]);
}

__global__ void finalize_kernel(const int* __restrict__ counts, const float* __restrict__ sqacc,
                                float* __restrict__ out, long outN) {
    __shared__ float sh[512];
    int tid = threadIdx.x;
    float p = (float)counts[tid] / 960.f;
    sh[tid] = p * logf(p + 1e-10f);
    __syncthreads();
    for (int off = 256; off > 0; off >>= 1) {
        if (tid < off) sh[tid] += sh[tid+off];
        __syncthreads();
    }
    if (tid == 0) {
        out[0] = 1.25f * sqacc[0] / (float)(POS2*64);
        out[outN-1] = expf(-sh[0]);
    }
}

// ---------------- convT gathers ----------------
__global__ void gather_t1_kernel(const float* __restrict__ Y1, const float* __restrict__ bias,
                                 float* __restrict__ t1) {
    int t = blockIdx.x * blockDim.x + threadIdx.x;
    if (t >= POSD*16) return;
    int oc = (t & 15) * 4;
    int pos = t >> 4;
    int ow = pos % TW; int r = pos / TW;
    int oh = r % TH; int b = r / TH;
    float4 acc = *(const float4*)(bias + oc);
    int lo = oh - 10;
    int ih_lo = lo <= 0 ? 0 : (lo + 9)/10;
    int ih_hi = (oh + 1)/10; if (ih_hi > 4) ih_hi = 4;
    int lw = ow - 10;
    int iw_lo = lw <= 0 ? 0 : (lw + 9)/10;
    int iw_hi = (ow + 1)/10; if (iw_hi > 5) iw_hi = 5;
    for (int ih = ih_lo; ih <= ih_hi; ih++) {
        int kh = oh + 1 - 10*ih;
        for (int iw = iw_lo; iw <= iw_hi; iw++) {
            int kw = ow + 1 - 10*iw;
            float4 y = *(const float4*)(Y1 + (size_t)((b*5 + ih)*6 + iw)*NT1 + (kh*12 + kw)*64 + oc);
            acc.x += y.x; acc.y += y.y; acc.z += y.z; acc.w += y.w;
        }
    }
    acc.x = fmaxf(acc.x, 0.f); acc.y = fmaxf(acc.y, 0.f);
    acc.z = fmaxf(acc.z, 0.f); acc.w = fmaxf(acc.w, 0.f);
    *(float4*)(t1 + (size_t)pos*64 + oc) = acc;
}

__global__ void gather_recon_kernel(const float* __restrict__ Y2, const float* __restrict__ bias,
                                    float* __restrict__ out) {
    long t = (long)blockIdx.x * blockDim.x + threadIdx.x;
    if (t >= (long)RECON_N) return;
    int ow = (int)(t % OWW); long r = t / OWW;
    int oh = (int)(r % OHH); r /= OHH;
    int oc = (int)(r % 2); int b = (int)(r / 2);
    float acc = bias[oc];
    int lo = oh - 8;
    int ih_lo = lo <= 0 ? 0 : (lo + 7)/8;
    int ih_hi = (oh + 1)/8; if (ih_hi > 49) ih_hi = 49;
    int lw = ow - 9;
    int iw_lo = lw <= 0 ? 0 : (lw + 8)/9;
    int iw_hi = (ow + 1)/9; if (iw_hi > 59) iw_hi = 59;
    for (int ih = ih_lo; ih <= ih_hi; ih++) {
        int kh = oh + 1 - 8*ih;
        for (int iw = iw_lo; iw <= iw_hi; iw++) {
            int kw = ow + 1 - 9*iw;
            acc += Y2[(size_t)((b*TH + ih)*TW + iw)*NT2 + (kh*11 + kw)*2 + oc];
        }
    }
    out[t] = acc;
}

// ---------------- host ----------------
static inline void launch_gemm128(const float* A, const float* B, float* C,
                                  int M, int N, int K, const float* bias,
                                  int reluOut, int reluA) {
    dim3 grid((N + 63)/64, (M + 127)/128);
    gemm128_kernel<<<grid, 128>>>(A, B, C, M, N, K, bias, reluOut, reluA);
}

static inline void launch_gemm3x_splitk(const float* A, const float* B, float* C, float* part,
                                        int M, int N, int K, int S, const float* bias,
                                        int reluOut, int reluA, int addC) {
    int Kc = (K + S - 1) / S;
    Kc = ((Kc + 15) / 16) * 16;
    S  = (K + Kc - 1) / Kc;
    dim3 grid((N + 63)/64, (M + 127)/128, S);
    gemm3x_kernel<<<grid, 256>>>(A, B, part, M, N, K, Kc, 0, 0, reluA);
    int MN = M * N;
    reduce_splitk_kernel<<<(MN + 255)/256, 256>>>(part, C, MN, N, S, bias, reluOut, addC);
}

static inline void launch_gemm_splitk(const float* A, const float* B, float* C, float* part,
                                      int M, int N, int K, int S, const float* bias,
                                      int reluOut, int addC) {
    int Kc = (K + S - 1) / S;
    Kc = ((Kc + 15) / 16) * 16;
    S  = (K + Kc - 1) / Kc;
    dim3 grid((N + 63)/64, (M + 63)/64, S);
    gemm_splitk_kernel<<<grid, 128>>>(A, B, part, M, N, K, Kc);
    int MN = M * N;
    reduce_splitk_kernel<<<(MN + 255)/256, 256>>>(part, C, MN, N, S, bias, reluOut, addC);
}

static inline void launch_gemm_tf32(const float* A, const float* B, float* C,
                                    int M, int N, int K, int reluA) {
    dim3 grid((N + 63)/64, (M + 127)/128);
    gemm_tf32_kernel<<<grid, 256>>>(A, B, C, M, N, K, reluA);
}

static inline void launch_gemm(const float* A, const float* B, float* C,
                               int M, int N, int K, const float* bias,
                               int reluOut, int reluA, int addC) {
    dim3 grid((N + 63)/64, (M + 63)/64);
    gemm_kernel<<<grid, 128>>>(A, B, C, M, N, K, bias, reluOut, reluA, addC);
}

template<int H,int W,int C,int KH,int KW,int SH,int SW,int OH,int OW,int RELU>
static inline void launch_im2col4(const float* in, float* out) {
    int total4 = NB*OH*OW*KH*KW*(C/4);
    im2col4_kernel<H,W,C,KH,KW,SH,SW,OH,OW,RELU><<<(total4+255)/256, 256>>>(in, out, total4);
}

extern "C" void kernel_launch(void* const* d_in, const int* in_sizes, int n_in,
                              void* d_out, int out_size) {
    const float* x       = (const float*)d_in[0];
    const float* enc_w1  = (const float*)d_in[1];
    const float* enc_b1  = (const float*)d_in[2];
    const float* enc_w2  = (const float*)d_in[3];
    const float* enc_b2  = (const float*)d_in[4];
    const float* enc_w3  = (const float*)d_in[5];
    const float* enc_b3  = (const float*)d_in[6];
    const float* enc_rw1 = (const float*)d_in[7];
    const float* enc_rw2 = (const float*)d_in[8];
    const float* pre_w   = (const float*)d_in[9];
    const float* pre_b   = (const float*)d_in[10];
    const float* emb     = (const float*)d_in[11];
    const float* dec_w1  = (const float*)d_in[12];
    const float* dec_b1  = (const float*)d_in[13];
    const float* dec_rw1 = (const float*)d_in[14];
    const float* dec_rw2 = (const float*)d_in[15];
    const float* dec_tw1 = (const float*)d_in[16];
    const float* dec_tb1 = (const float*)d_in[17];
    const float* dec_tw2 = (const float*)d_in[18];
    const float* dec_tb2 = (const float*)d_in[19];
    float* out = (float*)d_out;

    float *p_A1, *p_h1, *p_col, *p_hA, *p_hB, *p_t64, *p_z, *p_q, *p_part;
    float *p_Y1, *p_t1, *p_Y2;
    float *p_w1t, *p_w2t, *p_w3t, *p_er1t, *p_er2t, *p_pret, *p_d1t, *p_dr1t, *p_dr2t;
    float *p_tw1t, *p_tw2t, *p_esq, *p_sqacc;
    int *p_counts, *p_idx;
    cudaGetSymbolAddress((void**)&p_A1, g_A1);
    cudaGetSymbolAddress((void**)&p_h1, g_h1);
    cudaGetSymbolAddress((void**)&p_col, g_col);
    cudaGetSymbolAddress((void**)&p_hA, g_hA);
    cudaGetSymbolAddress((void**)&p_hB, g_hB);
    cudaGetSymbolAddress((void**)&p_t64, g_t64);
    cudaGetSymbolAddress((void**)&p_z, g_z);
    cudaGetSymbolAddress((void**)&p_q, g_q);
    cudaGetSymbolAddress((void**)&p_part, g_part);
    cudaGetSymbolAddress((void**)&p_Y1, g_Y1);
    cudaGetSymbolAddress((void**)&p_t1, g_t1);
    cudaGetSymbolAddress((void**)&p_Y2, g_Y2);
    cudaGetSymbolAddress((void**)&p_w1t, g_w1t);
    cudaGetSymbolAddress((void**)&p_w2t, g_w2t);
    cudaGetSymbolAddress((void**)&p_w3t, g_w3t);
    cudaGetSymbolAddress((void**)&p_er1t, g_er1t);
    cudaGetSymbolAddress((void**)&p_er2t, g_er2t);
    cudaGetSymbolAddress((void**)&p_pret, g_pret);
    cudaGetSymbolAddress((void**)&p_d1t, g_d1t);
    cudaGetSymbolAddress((void**)&p_dr1t, g_dr1t);
    cudaGetSymbolAddress((void**)&p_dr2t, g_dr2t);
    cudaGetSymbolAddress((void**)&p_tw1t, g_tw1t);
    cudaGetSymbolAddress((void**)&p_tw2t, g_tw2t);
    cudaGetSymbolAddress((void**)&p_esq, g_esq);
    cudaGetSymbolAddress((void**)&p_sqacc, g_sqacc);
    cudaGetSymbolAddress((void**)&p_counts, g_counts);
    cudaGetSymbolAddress((void**)&p_idx, g_idx);

    // ---- ONE merged weight-transpose kernel ----
    {
        TJobs J;
        int j = 0;
        long off = 0;
        auto add = [&](const float* s, float* d, int co, int ci, int kh, int kw, int isT) {
            J.src[j] = s; J.dst[j] = d;
            J.cout[j] = co; J.cin[j] = ci; J.kh[j] = kh; J.kw[j] = kw; J.isT[j] = isT;
            J.off[j] = off;
            off += (long)co*ci*kh*kw;
            j++;
        };
        add(enc_w1,            p_w1t,            64, 2,  10, 11, 0);
        add(enc_w2,            p_w2t,            128,64, 12, 12, 0);
        add(enc_w3,            p_w3t,            128,128, 3,  3, 0);
        add(enc_rw1,           p_er1t,            64,128, 3,  3, 0);
        add(enc_rw1 + 73728,   p_er1t + 73728,    64,128, 3,  3, 0);
        add(enc_rw2,           p_er2t,           128, 64, 1,  1, 0);
        add(enc_rw2 + 8192,    p_er2t + 8192,    128, 64, 1,  1, 0);
        add(pre_w,             p_pret,            64,128, 1,  1, 0);
        add(dec_w1,            p_d1t,            128, 64, 3,  3, 0);
        add(dec_rw1,           p_dr1t,            64,128, 3,  3, 0);
        add(dec_rw1 + 73728,   p_dr1t + 73728,    64,128, 3,  3, 0);
        add(dec_rw2,           p_dr2t,           128, 64, 1,  1, 0);
        add(dec_rw2 + 8192,    p_dr2t + 8192,    128, 64, 1,  1, 0);
        add(dec_tw1,           p_tw1t,            64,128, 12, 12, 1);
        add(dec_tw2,           p_tw2t,             2, 64, 10, 11, 1);
        J.off[NJOBS] = off;
        long blocks = (off + 255)/256;
        wtrans_all_kernel<<<(unsigned)blocks, 256>>>(J);
    }

    // ---- encoder (fp32-accurate; safe for VQ argmin) ----
    {
        int total2 = POS1 * (K1/2);
        im2col_c1_kernel<<<(total2 + 255)/256, 256>>>(x, p_A1);
    }
    launch_gemm128(p_A1, p_w1t, p_h1, POS1, OC1, K1, enc_b1, 1, 0);

    launch_im2col4<H1,W1,64,12,12,10,10,H2,W2,0>(p_h1, p_col);
    launch_gemm3x_splitk(p_col, p_w2t, p_hA, p_part, POS2, 128, K2, 16, enc_b2, 1, 0, 0);

    launch_im2col4<H2,W2,128,3,3,1,1,H2,W2,0>(p_hA, p_col);
    launch_gemm_splitk(p_col, p_w3t, p_hB, p_part, POS2, 128, 1152, 8, enc_b3, 0, 0);

    for (int i = 0; i < 2; i++) {
        launch_im2col4<H2,W2,128,3,3,1,1,H2,W2,1>(p_hB, p_col);
        launch_gemm_splitk(p_col, p_er1t + i*1152*64, p_t64, p_part, POS2, 64, 1152, 8, 0, 1, 0);
        launch_gemm(p_t64, p_er2t + i*64*128, p_hB, POS2, 128, 64, 0, 0, 0, 1);
    }
    launch_gemm(p_hB, p_pret, p_z, POS2, 64, 128, pre_b, 0, 1, 0);

    // ---- VQ ----
    vq_setup_kernel<<<1, KE>>>(emb, p_esq, p_counts, p_sqacc);
    vq_kernel<<<POS2, 128>>>(p_z, emb, p_esq, p_idx, p_q, p_counts, p_sqacc);
    finalize_kernel<<<1, KE>>>(p_counts, p_sqacc, out, (long)out_size);

    // ---- decoder ----
    launch_im2col4<H2,W2,64,3,3,1,1,H2,W2,0>(p_q, p_col);
    launch_gemm_splitk(p_col, p_d1t, p_hA, p_part, POS2, 128, 576, 4, dec_b1, 0, 0);

    for (int i = 0; i < 2; i++) {
        launch_im2col4<H2,W2,128,3,3,1,1,H2,W2,1>(p_hA, p_col);
        launch_gemm_splitk(p_col, p_dr1t + i*1152*64, p_t64, p_part, POS2, 64, 1152, 8, 0, 1, 0);
        launch_gemm(p_t64, p_dr2t + i*64*128, p_hA, POS2, 128, 64, 0, 0, 0, 1);
    }

    // convT1: tf32 GEMM (relu on input) + gather (+bias, relu)
    launch_gemm_tf32(p_hA, p_tw1t, p_Y1, POS2, NT1, 128, 1);
    gather_t1_kernel<<<(POSD*16 + 255)/256, 256>>>(p_Y1, dec_tb1, p_t1);

    // convT2: tf32 GEMM + gather (+bias) -> recon at out+1
    launch_gemm_tf32(p_t1, p_tw2t, p_Y2, POSD, NT2, 64, 0);
    {
        long tot = (long)RECON_N;
        gather_recon_kernel<<<(unsigned)((tot+255)/256), 256>>>(p_Y2, dec_tb2, out + 1);
    }
}